// round 15
// baseline (speedup 1.0000x reference)
#include <cuda_runtime.h>
#include <cuda_bf16.h>
#include <cstdint>

// Problem dims (fixed)
#define NN   8192
#define EE   262144
#define TDIM 256
#define HDIM 2048
#define ODIM 1024
#define LDIM 128

// ---------------- scratch (static, no allocations) ----------------
__device__ float g_H[NN * HDIM];                 // GEMM1 fp32 output
__device__ float g_X[NN * HDIM];                 // conv fp32 output (gather input)
__device__ __nv_bfloat16 g_Ahi[NN * HDIM];
__device__ __nv_bfloat16 g_Alo[NN * HDIM];
#define WTOT 24903680
__device__ __nv_bfloat16 g_Whi[WTOT];
__device__ __nv_bfloat16 g_Wlo[WTOT];
__device__ float g_bias2[2 * LDIM];              // packed bm|bv
__device__ int g_rowptr[NN + 1];
__device__ int g_cursor[NN];     // zero at module load; re-zeroed at END of each call
__device__ int g_srcsorted[EE];

// ---------------- PTX helpers (base sm_103 feature set ONLY) ----------------
__device__ __forceinline__ uint32_t smem_to_u32(const void* p) {
    uint32_t a;
    asm("{ .reg .u64 t; cvta.to.shared.u64 t, %1; cvt.u32.u64 %0, t; }" : "=r"(a) : "l"(p));
    return a;
}
#define CP_ASYNC16(dst, src) \
    asm volatile("cp.async.cg.shared.global [%0], [%1], 16;" :: "r"(dst), "l"(src))
#define CP_COMMIT() asm volatile("cp.async.commit_group;" ::: "memory")
#define CP_WAIT1()  asm volatile("cp.async.wait_group 1;" ::: "memory")
#define LDSM4(r0, r1, r2, r3, addr) \
    asm volatile("ldmatrix.sync.aligned.m8n8.x4.shared.b16 {%0,%1,%2,%3}, [%4];" \
        : "=r"(r0), "=r"(r1), "=r"(r2), "=r"(r3) : "r"(addr))
#define MMA_BF16(d, a0, a1, a2, a3, b0, b1) \
    asm volatile("mma.sync.aligned.m16n8k16.row.col.f32.bf16.bf16.f32 " \
        "{%0,%1,%2,%3},{%4,%5,%6,%7},{%8,%9},{%0,%1,%2,%3};" \
        : "+f"((d)[0]), "+f"((d)[1]), "+f"((d)[2]), "+f"((d)[3]) \
        : "r"(a0), "r"(a1), "r"(a2), "r"(a3), "r"(b0), "r"(b1))

// ---------------- CSR build ----------------
__global__ void k_count(const int* __restrict__ dstArr) {
    int e = blockIdx.x * blockDim.x + threadIdx.x;
    if (e < EE) atomicAdd(&g_cursor[dstArr[e]], 1);
}
__global__ void k_scan() {
    __shared__ int sh[1024];
    int tid = threadIdx.x;
    int carry = 0;
    for (int chunk = 0; chunk < NN / 1024; ++chunk) {
        int i = chunk * 1024 + tid;
        int v = g_cursor[i];
        sh[tid] = v;
        __syncthreads();
        for (int off = 1; off < 1024; off <<= 1) {
            int t = (tid >= off) ? sh[tid - off] : 0;
            __syncthreads();
            sh[tid] += t;
            __syncthreads();
        }
        int excl = sh[tid] - v;
        g_rowptr[i] = carry + excl;
        g_cursor[i] = carry + excl;
        int total = sh[1023];
        __syncthreads();
        carry += total;
    }
    if (tid == 0) g_rowptr[NN] = carry;
}
__global__ void k_place(const int* __restrict__ srcArr, const int* __restrict__ dstArr) {
    int e = blockIdx.x * blockDim.x + threadIdx.x;
    if (e < EE) {
        int p = atomicAdd(&g_cursor[dstArr[e]], 1);
        g_srcsorted[p] = srcArr[e];
    }
}
__global__ void k_zero_cursor() {
    int i = blockIdx.x * blockDim.x + threadIdx.x;
    if (i < NN) g_cursor[i] = 0;
}

// ---------------- hi/lo store helper ----------------
__device__ __forceinline__ void store_hilo4(float4 a, __nv_bfloat16* hi, __nv_bfloat16* lo, size_t e0) {
    __nv_bfloat16 hx = __float2bfloat16(a.x), hy = __float2bfloat16(a.y),
                  hz = __float2bfloat16(a.z), hw = __float2bfloat16(a.w);
    __nv_bfloat162 h01; h01.x = hx; h01.y = hy;
    __nv_bfloat162 h23; h23.x = hz; h23.y = hw;
    __nv_bfloat162 l01, l23;
    l01.x = __float2bfloat16(a.x - __bfloat162float(hx));
    l01.y = __float2bfloat16(a.y - __bfloat162float(hy));
    l23.x = __float2bfloat16(a.z - __bfloat162float(hz));
    l23.y = __float2bfloat16(a.w - __bfloat162float(hw));
    *(__nv_bfloat162*)(hi + e0) = h01;
    *(__nv_bfloat162*)(hi + e0 + 2) = h23;
    *(__nv_bfloat162*)(lo + e0) = l01;
    *(__nv_bfloat162*)(lo + e0 + 2) = l23;
}

// ---------------- gather (layer 0, din4=64): 4 nodes/block, 64 threads/node ----------------
__global__ __launch_bounds__(256) void k_gather_small(const float4* __restrict__ x4,
                                                      __nv_bfloat16* __restrict__ hi,
                                                      __nv_bfloat16* __restrict__ lo) {
    int t = threadIdx.x;
    int node = blockIdx.x * 4 + (t >> 6);
    int lane = t & 63;
    int begin = g_rowptr[node], end = g_rowptr[node + 1];
    size_t base = (size_t)node * 64;
    float4 acc = x4[base + lane];
    float4 acc2 = make_float4(0.f, 0.f, 0.f, 0.f);
    int e = begin;
    for (; e + 1 < end; e += 2) {
        size_t s0 = (size_t)g_srcsorted[e] * 64;
        size_t s1 = (size_t)g_srcsorted[e + 1] * 64;
        float4 v0 = x4[s0 + lane];
        float4 v1 = x4[s1 + lane];
        acc.x += v0.x;  acc.y += v0.y;  acc.z += v0.z;  acc.w += v0.w;
        acc2.x += v1.x; acc2.y += v1.y; acc2.z += v1.z; acc2.w += v1.w;
    }
    if (e < end) {
        size_t s0 = (size_t)g_srcsorted[e] * 64;
        float4 v0 = x4[s0 + lane];
        acc.x += v0.x; acc.y += v0.y; acc.z += v0.z; acc.w += v0.w;
    }
    acc.x += acc2.x; acc.y += acc2.y; acc.z += acc2.z; acc.w += acc2.w;
    store_hilo4(acc, hi, lo, (base + lane) * 4);
}

// ---------------- gather (din4=512): precomputed offsets + unroll2 dual accumulators ----------------
__global__ __launch_bounds__(256) void k_gather_big(const float4* __restrict__ x4,
                                                    __nv_bfloat16* __restrict__ hi,
                                                    __nv_bfloat16* __restrict__ lo) {
    __shared__ long long offs[512];
    int node = blockIdx.x;
    int begin = g_rowptr[node];
    int deg = g_rowptr[node + 1] - begin;
    int t = threadIdx.x;
    size_t base = (size_t)node * 512;
    float4 a0 = x4[base + t];
    float4 a1 = x4[base + t + 256];
    float4 b0 = make_float4(0.f, 0.f, 0.f, 0.f);
    float4 b1 = b0;
    for (int off = 0; off < deg; off += 512) {
        int cnt = min(deg - off, 512);
        __syncthreads();
        for (int i = t; i < cnt; i += 256)
            offs[i] = (long long)g_srcsorted[begin + off + i] * 512;
        __syncthreads();
        int e = 0;
        for (; e + 1 < cnt; e += 2) {
            const float4* p0 = x4 + offs[e];
            const float4* p1 = x4 + offs[e + 1];
            float4 v00 = p0[t], v01 = p0[t + 256];
            float4 v10 = p1[t], v11 = p1[t + 256];
            a0.x += v00.x; a0.y += v00.y; a0.z += v00.z; a0.w += v00.w;
            a1.x += v01.x; a1.y += v01.y; a1.z += v01.z; a1.w += v01.w;
            b0.x += v10.x; b0.y += v10.y; b0.z += v10.z; b0.w += v10.w;
            b1.x += v11.x; b1.y += v11.y; b1.z += v11.z; b1.w += v11.w;
        }
        if (e < cnt) {
            const float4* p0 = x4 + offs[e];
            float4 v00 = p0[t], v01 = p0[t + 256];
            a0.x += v00.x; a0.y += v00.y; a0.z += v00.z; a0.w += v00.w;
            a1.x += v01.x; a1.y += v01.y; a1.z += v01.z; a1.w += v01.w;
        }
    }
    a0.x += b0.x; a0.y += b0.y; a0.z += b0.z; a0.w += b0.w;
    a1.x += b1.x; a1.y += b1.y; a1.z += b1.z; a1.w += b1.w;
    store_hilo4(a0, hi, lo, (base + t) * 4);
    store_hilo4(a1, hi, lo, (base + t + 256) * 4);
}

// ---------------- split fp32 -> bf16 hi + lo ----------------
__global__ void k_split(const float* __restrict__ a, __nv_bfloat16* __restrict__ hi,
                        __nv_bfloat16* __restrict__ lo, int n) {
    int i = blockIdx.x * blockDim.x + threadIdx.x;
    if (i < n) {
        float v = a[i];
        __nv_bfloat16 h = __float2bfloat16(v);
        hi[i] = h;
        lo[i] = __float2bfloat16(v - __bfloat162float(h));
    }
}

// transpose + split: w [K x N] fp32 -> hiT/loT [N x K] bf16
__global__ void k_splitT(const float* __restrict__ w, __nv_bfloat16* __restrict__ hiT,
                         __nv_bfloat16* __restrict__ loT, int K, int N) {
    __shared__ float sm[32][33];
    int k0 = blockIdx.x * 32, n0 = blockIdx.y * 32;
    int tx = threadIdx.x, ty = threadIdx.y;  // 32 x 8
#pragma unroll
    for (int i = 0; i < 4; i++)
        sm[ty + i * 8][tx] = w[(size_t)(k0 + ty + i * 8) * N + n0 + tx];
    __syncthreads();
#pragma unroll
    for (int i = 0; i < 4; i++) {
        float v = sm[tx][ty + i * 8];
        __nv_bfloat16 h = __float2bfloat16(v);
        size_t o = (size_t)(n0 + ty + i * 8) * K + k0 + tx;
        hiT[o] = h;
        loT[o] = __float2bfloat16(v - __bfloat162float(h));
    }
}

__global__ void k_packbias(const float* __restrict__ bm, const float* __restrict__ bv) {
    int i = threadIdx.x;
    g_bias2[i] = (i < LDIM) ? bm[i] : bv[i - LDIM];
}

// ---------------- HMMA GEMM: C[M,Nc] = A @ B^T + bias ----------------
// DUAL: Nc==256, cols [0,128)->C stride 128, cols [128,256)->C2 stride 128 (uniform per CTA).
#define CHUNK   64
#define TSTRIDE 144
#define TILE_B  (128 * TSTRIDE)
#define STAGE_B (4 * TILE_B)
#define SMEM_HMMA (2 * STAGE_B)

__device__ __forceinline__ void stage_load(uint32_t sb, int s,
                                           const __nv_bfloat16* const* gsrc,
                                           int K, int kc, int tid) {
    uint32_t base = sb + s * STAGE_B;
#pragma unroll
    for (int t = 0; t < 4; t++) {
        const __nv_bfloat16* g = gsrc[t] + kc;
        uint32_t tb = base + t * TILE_B;
#pragma unroll
        for (int it = 0; it < 4; it++) {
            int l = tid + it * 256;
            int row = l >> 3, c = l & 7;
            uint32_t dst = tb + row * TSTRIDE + c * 16;
            const char* src = (const char*)(g + (size_t)row * K) + c * 16;
            CP_ASYNC16(dst, src);
        }
    }
}

template <bool RELU, bool DUAL>
__global__ __launch_bounds__(256) void k_hmma(
    const __nv_bfloat16* __restrict__ Ahi, const __nv_bfloat16* __restrict__ Alo,
    const __nv_bfloat16* __restrict__ Bhi, const __nv_bfloat16* __restrict__ Blo,
    const float* __restrict__ bias, float* __restrict__ C, float* __restrict__ C2,
    int K, int Nc) {
    extern __shared__ char smem[];
    uint32_t sb = smem_to_u32(smem);
    int tid = threadIdx.x, lane = tid & 31, wid = tid >> 5;
    int warp_m = wid >> 2;
    int warp_n = wid & 3;
    int mBase = blockIdx.y * 128, nBase = blockIdx.x * 128;

    const __nv_bfloat16* gsrc[4] = {Ahi + (size_t)mBase * K, Alo + (size_t)mBase * K,
                                    Bhi + (size_t)nBase * K, Blo + (size_t)nBase * K};

    float acc[4][4][4];
#pragma unroll
    for (int i = 0; i < 4; i++)
#pragma unroll
        for (int j = 0; j < 4; j++)
#pragma unroll
            for (int r = 0; r < 4; r++) acc[i][j][r] = 0.f;

    int nch = K / CHUNK;
    stage_load(sb, 0, gsrc, K, 0, tid);
    CP_COMMIT();
    stage_load(sb, 1, gsrc, K, CHUNK, tid);
    CP_COMMIT();

    uint32_t aRow = (uint32_t)(warp_m * 64 + (lane & 15)) * TSTRIDE + ((lane >> 4) * 16);
    uint32_t bRow = (uint32_t)(warp_n * 32 + (lane & 15)) * TSTRIDE + ((lane >> 4) * 16);

    for (int i = 0; i < nch; i++) {
        int s = i & 1;
        CP_WAIT1();
        __syncthreads();
        uint32_t st = sb + s * STAGE_B;
        uint32_t aHiB = st + aRow;
        uint32_t aLoB = st + TILE_B + aRow;
        uint32_t bHiB = st + 2 * TILE_B + bRow;
        uint32_t bLoB = st + 3 * TILE_B + bRow;
#pragma unroll
        for (int ks = 0; ks < 4; ks++) {
            uint32_t kof = ks * 32;
            uint32_t afh[4][4], afl[4][4], bfh[2][4], bfl[2][4];
#pragma unroll
            for (int mi = 0; mi < 4; mi++) {
                LDSM4(afh[mi][0], afh[mi][1], afh[mi][2], afh[mi][3], aHiB + mi * (16 * TSTRIDE) + kof);
                LDSM4(afl[mi][0], afl[mi][1], afl[mi][2], afl[mi][3], aLoB + mi * (16 * TSTRIDE) + kof);
            }
#pragma unroll
            for (int pb = 0; pb < 2; pb++) {
                LDSM4(bfh[pb][0], bfh[pb][1], bfh[pb][2], bfh[pb][3], bHiB + pb * (16 * TSTRIDE) + kof);
                LDSM4(bfl[pb][0], bfl[pb][1], bfl[pb][2], bfl[pb][3], bLoB + pb * (16 * TSTRIDE) + kof);
            }
#pragma unroll
            for (int mi = 0; mi < 4; mi++)
#pragma unroll
                for (int nj = 0; nj < 4; nj++) {
                    int pb = nj >> 1, hf = nj & 1;
                    MMA_BF16(acc[mi][nj], afh[mi][0], afh[mi][1], afh[mi][2], afh[mi][3],
                             bfh[pb][hf], bfh[pb][hf + 2]);
                    MMA_BF16(acc[mi][nj], afh[mi][0], afh[mi][1], afh[mi][2], afh[mi][3],
                             bfl[pb][hf], bfl[pb][hf + 2]);
                    MMA_BF16(acc[mi][nj], afl[mi][0], afl[mi][1], afl[mi][2], afl[mi][3],
                             bfh[pb][hf], bfh[pb][hf + 2]);
                }
        }
        __syncthreads();
        if (i + 2 < nch) stage_load(sb, s, gsrc, K, (i + 2) * CHUNK, tid);
        CP_COMMIT();
    }

    int g = lane >> 2, t4 = lane & 3;
#pragma unroll
    for (int mi = 0; mi < 4; mi++) {
#pragma unroll
        for (int nj = 0; nj < 4; nj++) {
            int m0 = mBase + warp_m * 64 + mi * 16 + g;
            int n0 = nBase + warp_n * 32 + nj * 8 + t4 * 2;
            float bi0 = bias[n0], bi1 = bias[n0 + 1];
            float v0 = acc[mi][nj][0] + bi0;
            float v1 = acc[mi][nj][1] + bi1;
            float v2 = acc[mi][nj][2] + bi0;
            float v3 = acc[mi][nj][3] + bi1;
            if (RELU) {
                v0 = fmaxf(v0, 0.f); v1 = fmaxf(v1, 0.f);
                v2 = fmaxf(v2, 0.f); v3 = fmaxf(v3, 0.f);
            }
            if (DUAL) {
                float* d = (n0 < LDIM) ? C : C2;     // uniform per CTA (tile N=128)
                int nl = n0 & (LDIM - 1);
                *(float2*)&d[(size_t)m0 * LDIM + nl] = make_float2(v0, v1);
                *(float2*)&d[(size_t)(m0 + 8) * LDIM + nl] = make_float2(v2, v3);
            } else {
                *(float2*)&C[(size_t)m0 * Nc + n0] = make_float2(v0, v1);
                *(float2*)&C[(size_t)(m0 + 8) * Nc + n0] = make_float2(v2, v3);
            }
        }
    }
}

// ---------------- z = mean + var * eps ----------------
__global__ void k_reparam(const float* __restrict__ mean, const float* __restrict__ var,
                          const float* __restrict__ eps, float* __restrict__ z) {
    int i = blockIdx.x * blockDim.x + threadIdx.x;
    if (i < NN * LDIM) z[i] = mean[i] + var[i] * eps[i];
}

// ---------------- launch ----------------
extern "C" void kernel_launch(void* const* d_in, const int* in_sizes, int n_in,
                              void* d_out, int out_size) {
    (void)in_sizes; (void)n_in; (void)out_size;
    const float* x0  = (const float*)d_in[0];
    const int*   idx = (const int*)d_in[1];
    const int*   src = idx;
    const int*   dst = idx + EE;
    const float* w1[4] = {(const float*)d_in[2], (const float*)d_in[6],
                          (const float*)d_in[10], (const float*)d_in[14]};
    const float* b1[4] = {(const float*)d_in[3], (const float*)d_in[7],
                          (const float*)d_in[11], (const float*)d_in[15]};
    const float* w2[4] = {(const float*)d_in[4], (const float*)d_in[8],
                          (const float*)d_in[12], (const float*)d_in[16]};
    const float* b2[4] = {(const float*)d_in[5], (const float*)d_in[9],
                          (const float*)d_in[13], (const float*)d_in[17]};
    const float* wm  = (const float*)d_in[18];
    const float* bm  = (const float*)d_in[19];
    const float* wv  = (const float*)d_in[20];
    const float* bv  = (const float*)d_in[21];
    const float* eps = (const float*)d_in[22];

    float* out  = (float*)d_out;
    float* zout = out;
    float* mout = out + (size_t)NN * LDIM;
    float* vout = out + 2 * (size_t)NN * LDIM;

    void* p;
    cudaGetSymbolAddress(&p, g_H);   float* H = (float*)p;
    cudaGetSymbolAddress(&p, g_X);   float* X = (float*)p;
    cudaGetSymbolAddress(&p, g_Ahi); __nv_bfloat16* Ahi = (__nv_bfloat16*)p;
    cudaGetSymbolAddress(&p, g_Alo); __nv_bfloat16* Alo = (__nv_bfloat16*)p;
    cudaGetSymbolAddress(&p, g_Whi); __nv_bfloat16* Whi = (__nv_bfloat16*)p;
    cudaGetSymbolAddress(&p, g_Wlo); __nv_bfloat16* Wlo = (__nv_bfloat16*)p;
    cudaGetSymbolAddress(&p, g_bias2); float* bias2 = (float*)p;

    cudaFuncSetAttribute(k_hmma<true,  false>, cudaFuncAttributeMaxDynamicSharedMemorySize, SMEM_HMMA);
    cudaFuncSetAttribute(k_hmma<false, false>, cudaFuncAttributeMaxDynamicSharedMemorySize, SMEM_HMMA);
    cudaFuncSetAttribute(k_hmma<false, true>,  cudaFuncAttributeMaxDynamicSharedMemorySize, SMEM_HMMA);

    // weight arena offsets: w1_0 w2_0 w1_1 w2_1 w1_2 w2_2 w1_3 w2_3 wm wv (wm|wv contiguous)
    const size_t woff[10] = {0, 524288, 4718592, 8912896, 13107200, 17301504,
                             21495808, 23592960, 24641536, 24772608};
    const float* wsrc[10] = {w1[0], w2[0], w1[1], w2[1], w1[2], w2[2], w1[3], w2[3], wm, wv};
    const int    wK[10]   = {TDIM, HDIM, HDIM, HDIM, HDIM, HDIM, HDIM, ODIM, ODIM, ODIM};
    const int    wN[10]   = {HDIM, HDIM, HDIM, HDIM, HDIM, HDIM, ODIM, ODIM, LDIM, LDIM};
    dim3 tblk(32, 8);

    // --- launches 0-2: CSR build ---
    k_count<<<(EE + 255) / 256, 256>>>(dst);
    k_scan<<<1, 1024>>>();
    k_place<<<(EE + 255) / 256, 256>>>(src, dst);
    // --- launch 3: layer-0 gather (PROFILED) ---
    k_gather_small<<<NN / 4, 256>>>((const float4*)x0, Ahi, Alo);
    // --- weight splits + bias pack ---
    for (int i = 0; i < 10; i++) {
        dim3 tg(wK[i] / 32, wN[i] / 32);
        k_splitT<<<tg, tblk>>>(wsrc[i], Whi + woff[i], Wlo + woff[i], wK[i], wN[i]);
    }
    k_packbias<<<1, 2 * LDIM>>>(bm, bv);

    auto hmma = [&](int wi, const float* bias, float* Cout, int K, int Nc, bool relu) {
        dim3 g(Nc / 128, NN / 128);
        if (relu)
            k_hmma<true, false><<<g, 256, SMEM_HMMA>>>(Ahi, Alo, Whi + woff[wi], Wlo + woff[wi],
                                                       bias, Cout, nullptr, K, Nc);
        else
            k_hmma<false, false><<<g, 256, SMEM_HMMA>>>(Ahi, Alo, Whi + woff[wi], Wlo + woff[wi],
                                                        bias, Cout, nullptr, K, Nc);
    };
    auto split = [&](const float* a, int n) {
        k_split<<<(n + 255) / 256, 256>>>(a, Ahi, Alo, n);
    };

    // layer 0: 256 -> 2048 -> 2048
    hmma(0, b1[0], H, TDIM, HDIM, true);
    split(H, NN * HDIM);
    hmma(1, b2[0], X, HDIM, HDIM, true);     // inter-conv ReLU fused
    // layers 1, 2
    for (int l = 1; l <= 2; l++) {
        k_gather_big<<<NN, 256>>>((const float4*)X, Ahi, Alo);
        hmma(2 * l, b1[l], H, HDIM, HDIM, true);
        split(H, NN * HDIM);
        hmma(2 * l + 1, b2[l], X, HDIM, HDIM, true);
    }
    // layer 3: 2048 -> 1024 -> 1024, no ReLU on conv output
    k_gather_big<<<NN, 256>>>((const float4*)X, Ahi, Alo);
    hmma(6, b1[3], H, HDIM, ODIM, true);
    split(H, NN * ODIM);
    hmma(7, b2[3], X, ODIM, ODIM, false);
    // merged heads: [wm|wv] as one N=256 GEMM, dual destination
    split(X, NN * ODIM);
    {
        dim3 g(2, NN / 128);
        k_hmma<false, true><<<g, 256, SMEM_HMMA>>>(Ahi, Alo, Whi + woff[8], Wlo + woff[8],
                                                   bias2, mout, vout, ODIM, 2 * LDIM);
    }
    k_reparam<<<(NN * LDIM + 255) / 256, 256>>>(mout, vout, eps, zout);
    // restore invariant: cursor zero for the next call
    k_zero_cursor<<<(NN + 255) / 256, 256>>>();
}

// round 17
// speedup vs baseline: 1.5089x; 1.5089x over previous
#include <cuda_runtime.h>
#include <cuda_bf16.h>
#include <cstdint>

// Problem dims (fixed)
#define NN   8192
#define EE   262144
#define TDIM 256
#define HDIM 2048
#define ODIM 1024
#define LDIM 128

// ---------------- scratch (static, no allocations) ----------------
__device__ float g_H[NN * HDIM];                 // GEMM1 fp32 output
__device__ float g_X[NN * HDIM];                 // conv fp32 output (gather input)
__device__ __nv_bfloat16 g_Ahi[NN * HDIM];
__device__ __nv_bfloat16 g_Alo[NN * HDIM];
#define WTOT 24903680
__device__ __nv_bfloat16 g_Whi[WTOT];
__device__ __nv_bfloat16 g_Wlo[WTOT];
__device__ int g_rowptr[NN + 1];
__device__ int g_cursor[NN];     // zero at module load; re-zeroed at END of each call
__device__ int g_srcsorted[EE];

// ---------------- PTX helpers (base sm_103 feature set ONLY) ----------------
__device__ __forceinline__ uint32_t smem_to_u32(const void* p) {
    uint32_t a;
    asm("{ .reg .u64 t; cvta.to.shared.u64 t, %1; cvt.u32.u64 %0, t; }" : "=r"(a) : "l"(p));
    return a;
}
#define CP_ASYNC16(dst, src) \
    asm volatile("cp.async.cg.shared.global [%0], [%1], 16;" :: "r"(dst), "l"(src))
#define CP_COMMIT() asm volatile("cp.async.commit_group;" ::: "memory")
#define CP_WAIT1()  asm volatile("cp.async.wait_group 1;" ::: "memory")
#define LDSM4(r0, r1, r2, r3, addr) \
    asm volatile("ldmatrix.sync.aligned.m8n8.x4.shared.b16 {%0,%1,%2,%3}, [%4];" \
        : "=r"(r0), "=r"(r1), "=r"(r2), "=r"(r3) : "r"(addr))
#define MMA_BF16(d, a0, a1, a2, a3, b0, b1) \
    asm volatile("mma.sync.aligned.m16n8k16.row.col.f32.bf16.bf16.f32 " \
        "{%0,%1,%2,%3},{%4,%5,%6,%7},{%8,%9},{%0,%1,%2,%3};" \
        : "+f"((d)[0]), "+f"((d)[1]), "+f"((d)[2]), "+f"((d)[3]) \
        : "r"(a0), "r"(a1), "r"(a2), "r"(a3), "r"(b0), "r"(b1))

// ---------------- CSR build ----------------
__global__ void k_count(const int* __restrict__ dstArr) {
    int e = blockIdx.x * blockDim.x + threadIdx.x;
    if (e < EE) atomicAdd(&g_cursor[dstArr[e]], 1);
}
__global__ void k_scan() {
    __shared__ int sh[1024];
    int tid = threadIdx.x;
    int carry = 0;
    for (int chunk = 0; chunk < NN / 1024; ++chunk) {
        int i = chunk * 1024 + tid;
        int v = g_cursor[i];
        sh[tid] = v;
        __syncthreads();
        for (int off = 1; off < 1024; off <<= 1) {
            int t = (tid >= off) ? sh[tid - off] : 0;
            __syncthreads();
            sh[tid] += t;
            __syncthreads();
        }
        int excl = sh[tid] - v;
        g_rowptr[i] = carry + excl;
        g_cursor[i] = carry + excl;
        int total = sh[1023];
        __syncthreads();
        carry += total;
    }
    if (tid == 0) g_rowptr[NN] = carry;
}
__global__ void k_place(const int* __restrict__ srcArr, const int* __restrict__ dstArr) {
    int e = blockIdx.x * blockDim.x + threadIdx.x;
    if (e < EE) {
        int p = atomicAdd(&g_cursor[dstArr[e]], 1);
        g_srcsorted[p] = srcArr[e];
    }
}
__global__ void k_zero_cursor() {
    int i = blockIdx.x * blockDim.x + threadIdx.x;
    if (i < NN) g_cursor[i] = 0;
}

// ---------------- hi/lo store helper ----------------
__device__ __forceinline__ void store_hilo4(float4 a, __nv_bfloat16* hi, __nv_bfloat16* lo, size_t e0) {
    __nv_bfloat16 hx = __float2bfloat16(a.x), hy = __float2bfloat16(a.y),
                  hz = __float2bfloat16(a.z), hw = __float2bfloat16(a.w);
    __nv_bfloat162 h01; h01.x = hx; h01.y = hy;
    __nv_bfloat162 h23; h23.x = hz; h23.y = hw;
    __nv_bfloat162 l01, l23;
    l01.x = __float2bfloat16(a.x - __bfloat162float(hx));
    l01.y = __float2bfloat16(a.y - __bfloat162float(hy));
    l23.x = __float2bfloat16(a.z - __bfloat162float(hz));
    l23.y = __float2bfloat16(a.w - __bfloat162float(hw));
    *(__nv_bfloat162*)(hi + e0) = h01;
    *(__nv_bfloat162*)(hi + e0 + 2) = h23;
    *(__nv_bfloat162*)(lo + e0) = l01;
    *(__nv_bfloat162*)(lo + e0 + 2) = l23;
}

// ---------------- gather (layer 0, din4=64): 4 nodes/block, 64 threads/node ----------------
__global__ __launch_bounds__(256) void k_gather_small(const float4* __restrict__ x4,
                                                      __nv_bfloat16* __restrict__ hi,
                                                      __nv_bfloat16* __restrict__ lo) {
    int t = threadIdx.x;
    int node = blockIdx.x * 4 + (t >> 6);
    int lane = t & 63;
    int begin = g_rowptr[node], end = g_rowptr[node + 1];
    size_t base = (size_t)node * 64;
    float4 acc = x4[base + lane];
    float4 acc2 = make_float4(0.f, 0.f, 0.f, 0.f);
    int e = begin;
    for (; e + 1 < end; e += 2) {
        size_t s0 = (size_t)g_srcsorted[e] * 64;
        size_t s1 = (size_t)g_srcsorted[e + 1] * 64;
        float4 v0 = x4[s0 + lane];
        float4 v1 = x4[s1 + lane];
        acc.x += v0.x;  acc.y += v0.y;  acc.z += v0.z;  acc.w += v0.w;
        acc2.x += v1.x; acc2.y += v1.y; acc2.z += v1.z; acc2.w += v1.w;
    }
    if (e < end) {
        size_t s0 = (size_t)g_srcsorted[e] * 64;
        float4 v0 = x4[s0 + lane];
        acc.x += v0.x; acc.y += v0.y; acc.z += v0.z; acc.w += v0.w;
    }
    acc.x += acc2.x; acc.y += acc2.y; acc.z += acc2.z; acc.w += acc2.w;
    store_hilo4(acc, hi, lo, (base + lane) * 4);
}

// ---------------- gather (din4=512): precomputed offsets + unroll2 dual accumulators ----------------
__global__ __launch_bounds__(256) void k_gather_big(const float4* __restrict__ x4,
                                                    __nv_bfloat16* __restrict__ hi,
                                                    __nv_bfloat16* __restrict__ lo) {
    __shared__ long long offs[512];
    int node = blockIdx.x;
    int begin = g_rowptr[node];
    int deg = g_rowptr[node + 1] - begin;
    int t = threadIdx.x;
    size_t base = (size_t)node * 512;
    float4 a0 = x4[base + t];
    float4 a1 = x4[base + t + 256];
    float4 b0 = make_float4(0.f, 0.f, 0.f, 0.f);
    float4 b1 = b0;
    for (int off = 0; off < deg; off += 512) {
        int cnt = min(deg - off, 512);
        __syncthreads();
        for (int i = t; i < cnt; i += 256)
            offs[i] = (long long)g_srcsorted[begin + off + i] * 512;
        __syncthreads();
        int e = 0;
        for (; e + 1 < cnt; e += 2) {
            const float4* p0 = x4 + offs[e];
            const float4* p1 = x4 + offs[e + 1];
            float4 v00 = p0[t], v01 = p0[t + 256];
            float4 v10 = p1[t], v11 = p1[t + 256];
            a0.x += v00.x; a0.y += v00.y; a0.z += v00.z; a0.w += v00.w;
            a1.x += v01.x; a1.y += v01.y; a1.z += v01.z; a1.w += v01.w;
            b0.x += v10.x; b0.y += v10.y; b0.z += v10.z; b0.w += v10.w;
            b1.x += v11.x; b1.y += v11.y; b1.z += v11.z; b1.w += v11.w;
        }
        if (e < cnt) {
            const float4* p0 = x4 + offs[e];
            float4 v00 = p0[t], v01 = p0[t + 256];
            a0.x += v00.x; a0.y += v00.y; a0.z += v00.z; a0.w += v00.w;
            a1.x += v01.x; a1.y += v01.y; a1.z += v01.z; a1.w += v01.w;
        }
    }
    a0.x += b0.x; a0.y += b0.y; a0.z += b0.z; a0.w += b0.w;
    a1.x += b1.x; a1.y += b1.y; a1.z += b1.z; a1.w += b1.w;
    store_hilo4(a0, hi, lo, (base + t) * 4);
    store_hilo4(a1, hi, lo, (base + t + 256) * 4);
}

// ---------------- split fp32 -> bf16 hi + lo ----------------
__global__ void k_split(const float* __restrict__ a, __nv_bfloat16* __restrict__ hi,
                        __nv_bfloat16* __restrict__ lo, int n) {
    int i = blockIdx.x * blockDim.x + threadIdx.x;
    if (i < n) {
        float v = a[i];
        __nv_bfloat16 h = __float2bfloat16(v);
        hi[i] = h;
        lo[i] = __float2bfloat16(v - __bfloat162float(h));
    }
}

// transpose + split: w [K x N] fp32 -> hiT/loT [N x K] bf16
__global__ void k_splitT(const float* __restrict__ w, __nv_bfloat16* __restrict__ hiT,
                         __nv_bfloat16* __restrict__ loT, int K, int N) {
    __shared__ float sm[32][33];
    int k0 = blockIdx.x * 32, n0 = blockIdx.y * 32;
    int tx = threadIdx.x, ty = threadIdx.y;  // 32 x 8
#pragma unroll
    for (int i = 0; i < 4; i++)
        sm[ty + i * 8][tx] = w[(size_t)(k0 + ty + i * 8) * N + n0 + tx];
    __syncthreads();
#pragma unroll
    for (int i = 0; i < 4; i++) {
        float v = sm[tx][ty + i * 8];
        __nv_bfloat16 h = __float2bfloat16(v);
        size_t o = (size_t)(n0 + ty + i * 8) * K + k0 + tx;
        hiT[o] = h;
        loT[o] = __float2bfloat16(v - __bfloat162float(h));
    }
}

// ---------------- HMMA GEMM: C[M,Nc] = A @ B^T + bias (2 instantiations ONLY) ----------------
#define CHUNK   64
#define TSTRIDE 144
#define TILE_B  (128 * TSTRIDE)
#define STAGE_B (4 * TILE_B)
#define SMEM_HMMA (2 * STAGE_B)

__device__ __forceinline__ void stage_load(uint32_t sb, int s,
                                           const __nv_bfloat16* const* gsrc,
                                           int K, int kc, int tid) {
    uint32_t base = sb + s * STAGE_B;
#pragma unroll
    for (int t = 0; t < 4; t++) {
        const __nv_bfloat16* g = gsrc[t] + kc;
        uint32_t tb = base + t * TILE_B;
#pragma unroll
        for (int it = 0; it < 4; it++) {
            int l = tid + it * 256;
            int row = l >> 3, c = l & 7;
            uint32_t dst = tb + row * TSTRIDE + c * 16;
            const char* src = (const char*)(g + (size_t)row * K) + c * 16;
            CP_ASYNC16(dst, src);
        }
    }
}

template <bool RELU>
__global__ __launch_bounds__(256) void k_hmma(
    const __nv_bfloat16* __restrict__ Ahi, const __nv_bfloat16* __restrict__ Alo,
    const __nv_bfloat16* __restrict__ Bhi, const __nv_bfloat16* __restrict__ Blo,
    const float* __restrict__ bias, float* __restrict__ C, int K, int Nc) {
    extern __shared__ char smem[];
    uint32_t sb = smem_to_u32(smem);
    int tid = threadIdx.x, lane = tid & 31, wid = tid >> 5;
    int warp_m = wid >> 2;
    int warp_n = wid & 3;
    int mBase = blockIdx.y * 128, nBase = blockIdx.x * 128;

    const __nv_bfloat16* gsrc[4] = {Ahi + (size_t)mBase * K, Alo + (size_t)mBase * K,
                                    Bhi + (size_t)nBase * K, Blo + (size_t)nBase * K};

    float acc[4][4][4];
#pragma unroll
    for (int i = 0; i < 4; i++)
#pragma unroll
        for (int j = 0; j < 4; j++)
#pragma unroll
            for (int r = 0; r < 4; r++) acc[i][j][r] = 0.f;

    int nch = K / CHUNK;
    stage_load(sb, 0, gsrc, K, 0, tid);
    CP_COMMIT();
    stage_load(sb, 1, gsrc, K, CHUNK, tid);
    CP_COMMIT();

    uint32_t aRow = (uint32_t)(warp_m * 64 + (lane & 15)) * TSTRIDE + ((lane >> 4) * 16);
    uint32_t bRow = (uint32_t)(warp_n * 32 + (lane & 15)) * TSTRIDE + ((lane >> 4) * 16);

    for (int i = 0; i < nch; i++) {
        int s = i & 1;
        CP_WAIT1();
        __syncthreads();
        uint32_t st = sb + s * STAGE_B;
        uint32_t aHiB = st + aRow;
        uint32_t aLoB = st + TILE_B + aRow;
        uint32_t bHiB = st + 2 * TILE_B + bRow;
        uint32_t bLoB = st + 3 * TILE_B + bRow;
#pragma unroll
        for (int ks = 0; ks < 4; ks++) {
            uint32_t kof = ks * 32;
            uint32_t afh[4][4], afl[4][4], bfh[2][4], bfl[2][4];
#pragma unroll
            for (int mi = 0; mi < 4; mi++) {
                LDSM4(afh[mi][0], afh[mi][1], afh[mi][2], afh[mi][3], aHiB + mi * (16 * TSTRIDE) + kof);
                LDSM4(afl[mi][0], afl[mi][1], afl[mi][2], afl[mi][3], aLoB + mi * (16 * TSTRIDE) + kof);
            }
#pragma unroll
            for (int pb = 0; pb < 2; pb++) {
                LDSM4(bfh[pb][0], bfh[pb][1], bfh[pb][2], bfh[pb][3], bHiB + pb * (16 * TSTRIDE) + kof);
                LDSM4(bfl[pb][0], bfl[pb][1], bfl[pb][2], bfl[pb][3], bLoB + pb * (16 * TSTRIDE) + kof);
            }
#pragma unroll
            for (int mi = 0; mi < 4; mi++)
#pragma unroll
                for (int nj = 0; nj < 4; nj++) {
                    int pb = nj >> 1, hf = nj & 1;
                    MMA_BF16(acc[mi][nj], afh[mi][0], afh[mi][1], afh[mi][2], afh[mi][3],
                             bfh[pb][hf], bfh[pb][hf + 2]);
                    MMA_BF16(acc[mi][nj], afh[mi][0], afh[mi][1], afh[mi][2], afh[mi][3],
                             bfl[pb][hf], bfl[pb][hf + 2]);
                    MMA_BF16(acc[mi][nj], afl[mi][0], afl[mi][1], afl[mi][2], afl[mi][3],
                             bfh[pb][hf], bfh[pb][hf + 2]);
                }
        }
        __syncthreads();
        if (i + 2 < nch) stage_load(sb, s, gsrc, K, (i + 2) * CHUNK, tid);
        CP_COMMIT();
    }

    int g = lane >> 2, t4 = lane & 3;
#pragma unroll
    for (int mi = 0; mi < 4; mi++) {
#pragma unroll
        for (int nj = 0; nj < 4; nj++) {
            int m0 = mBase + warp_m * 64 + mi * 16 + g;
            int n0 = nBase + warp_n * 32 + nj * 8 + t4 * 2;
            float bi0 = bias[n0], bi1 = bias[n0 + 1];
            float v0 = acc[mi][nj][0] + bi0;
            float v1 = acc[mi][nj][1] + bi1;
            float v2 = acc[mi][nj][2] + bi0;
            float v3 = acc[mi][nj][3] + bi1;
            if (RELU) {
                v0 = fmaxf(v0, 0.f); v1 = fmaxf(v1, 0.f);
                v2 = fmaxf(v2, 0.f); v3 = fmaxf(v3, 0.f);
            }
            *(float2*)&C[(size_t)m0 * Nc + n0] = make_float2(v0, v1);
            *(float2*)&C[(size_t)(m0 + 8) * Nc + n0] = make_float2(v2, v3);
        }
    }
}

// ---------------- z = mean + var * eps ----------------
__global__ void k_reparam(const float* __restrict__ mean, const float* __restrict__ var,
                          const float* __restrict__ eps, float* __restrict__ z) {
    int i = blockIdx.x * blockDim.x + threadIdx.x;
    if (i < NN * LDIM) z[i] = mean[i] + var[i] * eps[i];
}

// ---------------- launch ----------------
extern "C" void kernel_launch(void* const* d_in, const int* in_sizes, int n_in,
                              void* d_out, int out_size) {
    (void)in_sizes; (void)n_in; (void)out_size;
    const float* x0  = (const float*)d_in[0];
    const int*   idx = (const int*)d_in[1];
    const int*   src = idx;
    const int*   dst = idx + EE;
    const float* w1[4] = {(const float*)d_in[2], (const float*)d_in[6],
                          (const float*)d_in[10], (const float*)d_in[14]};
    const float* b1[4] = {(const float*)d_in[3], (const float*)d_in[7],
                          (const float*)d_in[11], (const float*)d_in[15]};
    const float* w2[4] = {(const float*)d_in[4], (const float*)d_in[8],
                          (const float*)d_in[12], (const float*)d_in[16]};
    const float* b2[4] = {(const float*)d_in[5], (const float*)d_in[9],
                          (const float*)d_in[13], (const float*)d_in[17]};
    const float* wm  = (const float*)d_in[18];
    const float* bm  = (const float*)d_in[19];
    const float* wv  = (const float*)d_in[20];
    const float* bv  = (const float*)d_in[21];
    const float* eps = (const float*)d_in[22];

    float* out  = (float*)d_out;
    float* zout = out;
    float* mout = out + (size_t)NN * LDIM;
    float* vout = out + 2 * (size_t)NN * LDIM;

    void* p;
    cudaGetSymbolAddress(&p, g_H);   float* H = (float*)p;
    cudaGetSymbolAddress(&p, g_X);   float* X = (float*)p;
    cudaGetSymbolAddress(&p, g_Ahi); __nv_bfloat16* Ahi = (__nv_bfloat16*)p;
    cudaGetSymbolAddress(&p, g_Alo); __nv_bfloat16* Alo = (__nv_bfloat16*)p;
    cudaGetSymbolAddress(&p, g_Whi); __nv_bfloat16* Whi = (__nv_bfloat16*)p;
    cudaGetSymbolAddress(&p, g_Wlo); __nv_bfloat16* Wlo = (__nv_bfloat16*)p;

    cudaFuncSetAttribute(k_hmma<true>,  cudaFuncAttributeMaxDynamicSharedMemorySize, SMEM_HMMA);
    cudaFuncSetAttribute(k_hmma<false>, cudaFuncAttributeMaxDynamicSharedMemorySize, SMEM_HMMA);

    // weight arena offsets: w1_0 w2_0 w1_1 w2_1 w1_2 w2_2 w1_3 w2_3 wm wv
    const size_t woff[10] = {0, 524288, 4718592, 8912896, 13107200, 17301504,
                             21495808, 23592960, 24641536, 24772608};
    const float* wsrc[10] = {w1[0], w2[0], w1[1], w2[1], w1[2], w2[2], w1[3], w2[3], wm, wv};
    const int    wK[10]   = {TDIM, HDIM, HDIM, HDIM, HDIM, HDIM, HDIM, ODIM, ODIM, ODIM};
    const int    wN[10]   = {HDIM, HDIM, HDIM, HDIM, HDIM, HDIM, ODIM, ODIM, LDIM, LDIM};
    dim3 tblk(32, 8);

    // --- launches 0-2: CSR build ---
    k_count<<<(EE + 255) / 256, 256>>>(dst);
    k_scan<<<1, 1024>>>();
    k_place<<<(EE + 255) / 256, 256>>>(src, dst);
    // --- launch 3: layer-0 gather (PROFILED) ---
    k_gather_small<<<NN / 4, 256>>>((const float4*)x0, Ahi, Alo);
    // --- weight splits ---
    for (int i = 0; i < 10; i++) {
        dim3 tg(wK[i] / 32, wN[i] / 32);
        k_splitT<<<tg, tblk>>>(wsrc[i], Whi + woff[i], Wlo + woff[i], wK[i], wN[i]);
    }

    auto hmma = [&](int wi, const float* bias, float* Cout, int K, int Nc, bool relu) {
        dim3 g(Nc / 128, NN / 128);
        if (relu)
            k_hmma<true><<<g, 256, SMEM_HMMA>>>(Ahi, Alo, Whi + woff[wi], Wlo + woff[wi],
                                                bias, Cout, K, Nc);
        else
            k_hmma<false><<<g, 256, SMEM_HMMA>>>(Ahi, Alo, Whi + woff[wi], Wlo + woff[wi],
                                                 bias, Cout, K, Nc);
    };
    auto split = [&](const float* a, int n) {
        k_split<<<(n + 255) / 256, 256>>>(a, Ahi, Alo, n);
    };

    // layer 0: 256 -> 2048 -> 2048
    hmma(0, b1[0], H, TDIM, HDIM, true);
    split(H, NN * HDIM);
    hmma(1, b2[0], X, HDIM, HDIM, true);     // inter-conv ReLU fused
    // layers 1, 2
    for (int l = 1; l <= 2; l++) {
        k_gather_big<<<NN, 256>>>((const float4*)X, Ahi, Alo);
        hmma(2 * l, b1[l], H, HDIM, HDIM, true);
        split(H, NN * HDIM);
        hmma(2 * l + 1, b2[l], X, HDIM, HDIM, true);
    }
    // layer 3: 2048 -> 1024 -> 1024, no ReLU on conv output
    k_gather_big<<<NN, 256>>>((const float4*)X, Ahi, Alo);
    hmma(6, b1[3], H, HDIM, ODIM, true);
    split(H, NN * ODIM);
    hmma(7, b2[3], X, ODIM, ODIM, false);
    // heads: two separate N=128 GEMMs (2 instantiations total — matches R14 structure)
    split(X, NN * ODIM);
    {
        dim3 g(1, NN / 128);
        k_hmma<false><<<g, 256, SMEM_HMMA>>>(Ahi, Alo, Whi + woff[8], Wlo + woff[8],
                                             bm, mout, ODIM, LDIM);
        k_hmma<false><<<g, 256, SMEM_HMMA>>>(Ahi, Alo, Whi + woff[9], Wlo + woff[9],
                                             bv, vout, ODIM, LDIM);
    }
    k_reparam<<<(NN * LDIM + 255) / 256, 256>>>(mout, vout, eps, zout);
    // restore invariant: cursor zero for the next call
    k_zero_cursor<<<(NN + 255) / 256, 256>>>();
}